// round 16
// baseline (speedup 1.0000x reference)
#include <cuda_runtime.h>
#include <cstdint>

// ---------------------------------------------------------------------------
// HGCN layer, c_in = c_out = 1.  Two-bucket pipelined aggregation:
//   stream A: linear[0,h1) -> evH1 -> linear[h1,n) ------\
//   stream B: CSR(2n buckets) ... wait evH1 -> gather_A --+-> evGA
//   stream A: wait evGA -> gather_B_final (bucket B + agg + epilogue) -> out
//   stream B: tail (adj cast) -> evTail ; stream A waits evTail (capture join)
// Bucket A = edges with src < h1 (ready after linear half 1).
// adj is int32 (JAX w/o x64 downcasts int64 -> int32).
// ---------------------------------------------------------------------------

#define NMAX   50000
#define EMAX   800000
#define MAXN_F 0.996f     // (1 - 4e-3)/sqrt(c), c = 1
#define MINN   1e-15f
#define SCHUNK 1024
#define NBMAX  ((2 * NMAX + SCHUNK - 1) / SCHUNK + 2)

__device__ __align__(16) float g_ht [(size_t)NMAX * 128];
__device__ __align__(16) float g_agg[(size_t)NMAX * 128];
__device__ __align__(16) int g_cnt[2 * NMAX];
__device__ int   g_off[2 * NMAX + 1];
__device__ int   g_cur[2 * NMAX];
__device__ int   g_bsum[NBMAX];
__device__ __align__(8) int2 g_pair[EMAX];   // .x = src, .y = bitcast(weight)

__device__ __forceinline__ float artanh_f(float v) {
    v = fminf(fmaxf(v, -1.0f + 1e-7f), 1.0f - 1e-7f);
    return 0.5f * (log1pf(v) - log1pf(-v));
}

// ------------------------------------------------------- fused HypLinear ----
// bias -> hyp-bias transform computed per-block; rows [rbeg, rend).
__global__ __launch_bounds__(256, 2)
void k_linear(const float* __restrict__ x, const float* __restrict__ weight,
              const float* __restrict__ bias, int rbeg, int rend) {
    extern __shared__ float sm[];
    float* ws  = sm;                        // [128][132]  ws[k*132+j] = W[j][k]
    float* xs  = sm + 128 * 132;            // [64][132]
    float* hbs = sm + 128 * 132 + 64 * 132; // [128]
    __shared__ float s_red[4];
    const int tid  = threadIdx.x;
    const int row0 = rbeg + blockIdx.x * 64;
    const int lane = tid & 31;

    float bv = (tid < 128) ? bias[tid] : 0.0f;
    {
        float ss = bv * bv;
        #pragma unroll
        for (int off = 16; off; off >>= 1) ss += __shfl_xor_sync(0xffffffffu, ss, off);
        if (tid < 128 && lane == 0) s_red[tid >> 5] = ss;
    }
    __syncthreads();
    const float btot = s_red[0] + s_red[1] + s_red[2] + s_red[3];
    const float bn   = fmaxf(sqrtf(btot), MINN);
    const float teb  = tanhf(bn);
    float bf = teb / bn;
    if (teb > MAXN_F) bf *= MAXN_F / fmaxf(teb, MINN);
    const float hnb  = fminf(teb, MAXN_F);
    const float hbsq = hnb * hnb;
    if (tid < 128) hbs[tid] = bf * bv;

    for (int i = tid; i < 128 * 128; i += 256) {
        int j = i >> 7, k = i & 127;
        ws[k * 132 + j] = weight[i];
    }
    for (int i = tid; i < 64 * 128; i += 256) {
        int r = i >> 7, k = i & 127;
        int gr = row0 + r;
        xs[r * 132 + k] = (gr < rend) ? x[(size_t)gr * 128 + k] : 0.0f;
    }
    __syncthreads();

    const int w = tid >> 5;
    const int j0 = lane * 4;

    float x2[8];
    #pragma unroll
    for (int i = 0; i < 8; i++) {
        float4 xv = *(const float4*)&xs[(w * 8 + i) * 132 + j0];
        float p = xv.x * xv.x + xv.y * xv.y + xv.z * xv.z + xv.w * xv.w;
        #pragma unroll
        for (int off = 16; off; off >>= 1) p += __shfl_xor_sync(0xffffffffu, p, off);
        x2[i] = p;
    }

    float acc[8][4];
    #pragma unroll
    for (int i = 0; i < 8; i++)
        acc[i][0] = acc[i][1] = acc[i][2] = acc[i][3] = 0.f;

    for (int k = 0; k < 128; k += 4) {
        float4 b0 = *(const float4*)&ws[(k + 0) * 132 + j0];
        float4 b1 = *(const float4*)&ws[(k + 1) * 132 + j0];
        float4 b2 = *(const float4*)&ws[(k + 2) * 132 + j0];
        float4 b3 = *(const float4*)&ws[(k + 3) * 132 + j0];
        #pragma unroll
        for (int i = 0; i < 8; i++) {
            float4 a = *(const float4*)&xs[(w * 8 + i) * 132 + k];
            acc[i][0] = fmaf(a.x, b0.x, acc[i][0]);
            acc[i][1] = fmaf(a.x, b0.y, acc[i][1]);
            acc[i][2] = fmaf(a.x, b0.z, acc[i][2]);
            acc[i][3] = fmaf(a.x, b0.w, acc[i][3]);
            acc[i][0] = fmaf(a.y, b1.x, acc[i][0]);
            acc[i][1] = fmaf(a.y, b1.y, acc[i][1]);
            acc[i][2] = fmaf(a.y, b1.z, acc[i][2]);
            acc[i][3] = fmaf(a.y, b1.w, acc[i][3]);
            acc[i][0] = fmaf(a.z, b2.x, acc[i][0]);
            acc[i][1] = fmaf(a.z, b2.y, acc[i][1]);
            acc[i][2] = fmaf(a.z, b2.z, acc[i][2]);
            acc[i][3] = fmaf(a.z, b2.w, acc[i][3]);
            acc[i][0] = fmaf(a.w, b3.x, acc[i][0]);
            acc[i][1] = fmaf(a.w, b3.y, acc[i][1]);
            acc[i][2] = fmaf(a.w, b3.z, acc[i][2]);
            acc[i][3] = fmaf(a.w, b3.w, acc[i][3]);
        }
    }

    const float hb0 = hbs[j0 + 0], hb1 = hbs[j0 + 1],
                hb2c = hbs[j0 + 2], hb3 = hbs[j0 + 3];

    #pragma unroll
    for (int i = 0; i < 8; i++) {
        float sq = acc[i][0] * acc[i][0] + acc[i][1] * acc[i][1]
                 + acc[i][2] * acc[i][2] + acc[i][3] * acc[i][3];
        float db = acc[i][0] * hb0 + acc[i][1] * hb1
                 + acc[i][2] * hb2c + acc[i][3] * hb3;
        #pragma unroll
        for (int off = 16; off; off >>= 1) {
            sq += __shfl_xor_sync(0xffffffffu, sq, off);
            db += __shfl_xor_sync(0xffffffffu, db, off);
        }
        float xn  = fmaxf(sqrtf(x2[i]), MINN);
        float atx = artanh_f(xn);
        float mxn = fmaxf(sqrtf(sq), MINN);
        float t   = tanhf(mxn / xn * atx);
        float beta = t;
        if (fabsf(t) > MAXN_F) beta = copysignf(MAXN_F, t);
        float xy  = beta * (db / mxn);
        float b2  = beta * beta;
        float A   = 1.f + 2.f * xy + hbsq;
        float B   = 1.f - b2;
        float den = fmaxf(1.f + 2.f * xy + b2 * hbsq, MINN);
        float pc  = A * beta / (mxn * den);
        float qc  = B / den;
        float h2 = pc * pc * sq + 2.f * pc * qc * db + qc * qc * hbsq;
        float hn = fmaxf(sqrtf(h2), MINN);
        if (hn > MAXN_F) { float sc = MAXN_F / hn; pc *= sc; qc *= sc; hn = MAXN_F; }
        float gam = artanh_f(hn) / hn;
        float P = gam * pc, Q = gam * qc;

        int gr = row0 + w * 8 + i;
        if (gr < rend) {
            float4 o;
            o.x = P * acc[i][0] + Q * hb0;
            o.y = P * acc[i][1] + Q * hb1;
            o.z = P * acc[i][2] + Q * hb2c;
            o.w = P * acc[i][3] + Q * hb3;
            *(float4*)&g_ht[(size_t)gr * 128 + j0] = o;
        }
    }
}

// ------------------------------------------------------------- CSR build ---
__global__ void k_zero_cnt(int m) {
    int i = blockIdx.x * blockDim.x + threadIdx.x;
    if (i < m) g_cnt[i] = 0;
}

// 4 edges/thread, int4 loads (e % 4 == 0 fast path).
__global__ void k_hist(const int* __restrict__ adj, int e, int n, int split) {
    int base = (blockIdx.x * blockDim.x + threadIdx.x) * 4;
    if (base >= e) return;
    if (base + 3 < e && ((e & 3) == 0)) {
        int4 ss = *(const int4*)&adj[base];
        int4 rr = *(const int4*)&adj[e + base];
        int s[4] = {ss.x, ss.y, ss.z, ss.w};
        int r[4] = {rr.x, rr.y, rr.z, rr.w};
        #pragma unroll
        for (int j = 0; j < 4; j++)
            if ((unsigned)s[j] < (unsigned)n && (unsigned)r[j] < (unsigned)n)
                atomicAdd(&g_cnt[(s[j] >= split ? n : 0) + r[j]], 1);
    } else {
        for (int j = 0; j < 4 && base + j < e; j++) {
            int s = adj[base + j], r = adj[e + base + j];
            if ((unsigned)s < (unsigned)n && (unsigned)r < (unsigned)n)
                atomicAdd(&g_cnt[(s >= split ? n : 0) + r], 1);
        }
    }
}

__global__ __launch_bounds__(256)
void k_scan1(int m) {
    __shared__ int wsum[8];
    int blk = blockIdx.x, tid = threadIdx.x;
    int lane = tid & 31, wid = tid >> 5;
    int base = blk * SCHUNK + tid * 4;

    int v0 = 0, v1 = 0, v2 = 0, v3 = 0;
    if (base + 3 < m) {
        int4 t = *(const int4*)&g_cnt[base];
        v0 = t.x; v1 = t.y; v2 = t.z; v3 = t.w;
    } else {
        if (base + 0 < m) v0 = g_cnt[base + 0];
        if (base + 1 < m) v1 = g_cnt[base + 1];
        if (base + 2 < m) v2 = g_cnt[base + 2];
    }
    int tsum = v0 + v1 + v2 + v3;
    int x = tsum;
    #pragma unroll
    for (int off = 1; off < 32; off <<= 1) {
        int y = __shfl_up_sync(0xffffffffu, x, off);
        if (lane >= off) x += y;
    }
    if (lane == 31) wsum[wid] = x;
    __syncthreads();
    if (tid < 32) {
        int t = (tid < 8) ? wsum[tid] : 0;
        #pragma unroll
        for (int off = 1; off < 8; off <<= 1) {
            int y = __shfl_up_sync(0xffffffffu, t, off);
            if (lane >= off) t += y;
        }
        if (tid < 8) wsum[tid] = t;
    }
    __syncthreads();
    int excl = ((wid == 0) ? 0 : wsum[wid - 1]) + x - tsum;
    if (base + 0 < m) g_off[base + 0] = excl;  excl += v0;
    if (base + 1 < m) g_off[base + 1] = excl;  excl += v1;
    if (base + 2 < m) g_off[base + 2] = excl;  excl += v2;
    if (base + 3 < m) g_off[base + 3] = excl;
    __syncthreads();
    if (tid == 0) g_bsum[blk] = wsum[7];
}

__global__ void k_scan2(int nb) {
    int lane = threadIdx.x;   // 32 threads
    int carry = 0;
    for (int base = 0; base < nb; base += 32) {
        int v = (base + lane < nb) ? g_bsum[base + lane] : 0;
        int x = v;
        #pragma unroll
        for (int off = 1; off < 32; off <<= 1) {
            int y = __shfl_up_sync(0xffffffffu, x, off);
            if (lane >= off) x += y;
        }
        int excl = carry + x - v;
        if (base + lane < nb) g_bsum[base + lane] = excl;
        carry += __shfl_sync(0xffffffffu, x, 31);
    }
    if (lane == 0) g_bsum[nb] = carry;
}

__global__ void k_scan3(int m, int nb) {
    int i = blockIdx.x * blockDim.x + threadIdx.x;
    if (i < m) {
        int v = g_off[i] + g_bsum[i / SCHUNK];
        g_off[i] = v;
        g_cur[i] = v;
    }
    if (i == 0) g_off[m] = g_bsum[nb];
}

// 4 edges/thread, vector loads.
__global__ void k_fill(const int* __restrict__ adj, const float* __restrict__ w,
                       int e, int n, int split) {
    int base = (blockIdx.x * blockDim.x + threadIdx.x) * 4;
    if (base >= e) return;
    if (base + 3 < e && ((e & 3) == 0)) {
        int4 ss = *(const int4*)&adj[base];
        int4 rr = *(const int4*)&adj[e + base];
        float4 ww = *(const float4*)&w[base];
        int s[4] = {ss.x, ss.y, ss.z, ss.w};
        int r[4] = {rr.x, rr.y, rr.z, rr.w};
        float wv[4] = {ww.x, ww.y, ww.z, ww.w};
        #pragma unroll
        for (int j = 0; j < 4; j++)
            if ((unsigned)s[j] < (unsigned)n && (unsigned)r[j] < (unsigned)n) {
                int idx = (s[j] >= split ? n : 0) + r[j];
                int pos = atomicAdd(&g_cur[idx], 1);
                g_pair[pos] = make_int2(s[j], __float_as_int(wv[j]));
            }
    } else {
        for (int j = 0; j < 4 && base + j < e; j++) {
            int s = adj[base + j], r = adj[e + base + j];
            if ((unsigned)s < (unsigned)n && (unsigned)r < (unsigned)n) {
                int idx = (s >= split ? n : 0) + r;
                int pos = atomicAdd(&g_cur[idx], 1);
                g_pair[pos] = make_int2(s, __float_as_int(w[base + j]));
            }
        }
    }
}

// ---------------------------------------------- gather A: partial -> g_agg --
__global__ __launch_bounds__(256)
void k_gather_a(int n) {
    int gw   = (blockIdx.x * blockDim.x + threadIdx.x) >> 5;
    int lane = threadIdx.x & 31;
    if (gw >= n) return;
    int beg = g_off[gw], end = g_off[gw + 1];
    const int j4 = lane * 4;

    float4 u = make_float4(0.f, 0.f, 0.f, 0.f);
    for (int j = beg; j < end; j += 8) {
        int cnt = end - j; if (cnt > 8) cnt = 8;
        int2 p = make_int2(0, 0);
        if (lane < cnt) p = g_pair[j + lane];
        int srcs[8]; float wts[8];
        #pragma unroll
        for (int t = 0; t < 8; t++) {
            srcs[t] = __shfl_sync(0xffffffffu, p.x, t);
            wts[t]  = __int_as_float(__shfl_sync(0xffffffffu, p.y, t));
        }
        float4 v[8];
        #pragma unroll
        for (int t = 0; t < 8; t++)
            if (t < cnt) v[t] = *(const float4*)&g_ht[(size_t)srcs[t] * 128 + j4];
        #pragma unroll
        for (int t = 0; t < 8; t++)
            if (t < cnt) {
                u.x = fmaf(wts[t], v[t].x, u.x);
                u.y = fmaf(wts[t], v[t].y, u.y);
                u.z = fmaf(wts[t], v[t].z, u.z);
                u.w = fmaf(wts[t], v[t].w, u.w);
            }
    }
    *(float4*)&g_agg[(size_t)gw * 128 + j4] = u;   // always write (no zero pass)
}

// --------------------------- gather B + epilogue: bucket B + agg -> out -----
__global__ __launch_bounds__(256)
void k_gather_b_final(float* __restrict__ out, int n) {
    int gw   = (blockIdx.x * blockDim.x + threadIdx.x) >> 5;
    int lane = threadIdx.x & 31;
    if (gw >= n) return;
    int beg = g_off[n + gw], end = g_off[n + gw + 1];
    const int j4 = lane * 4;

    float4 u = *(const float4*)&g_agg[(size_t)gw * 128 + j4];
    for (int j = beg; j < end; j += 8) {
        int cnt = end - j; if (cnt > 8) cnt = 8;
        int2 p = make_int2(0, 0);
        if (lane < cnt) p = g_pair[j + lane];
        int srcs[8]; float wts[8];
        #pragma unroll
        for (int t = 0; t < 8; t++) {
            srcs[t] = __shfl_sync(0xffffffffu, p.x, t);
            wts[t]  = __int_as_float(__shfl_sync(0xffffffffu, p.y, t));
        }
        float4 v[8];
        #pragma unroll
        for (int t = 0; t < 8; t++)
            if (t < cnt) v[t] = *(const float4*)&g_ht[(size_t)srcs[t] * 128 + j4];
        #pragma unroll
        for (int t = 0; t < 8; t++)
            if (t < cnt) {
                u.x = fmaf(wts[t], v[t].x, u.x);
                u.y = fmaf(wts[t], v[t].y, u.y);
                u.z = fmaf(wts[t], v[t].z, u.z);
                u.w = fmaf(wts[t], v[t].w, u.w);
            }
    }

    // epilogue: proj(expmap0(u)) -> relu(logmap0) -> proj(expmap0)
    float s1 = u.x * u.x + u.y * u.y + u.z * u.z + u.w * u.w;
    #pragma unroll
    for (int off = 16; off; off >>= 1) s1 += __shfl_xor_sync(0xffffffffu, s1, off);
    float un = fmaxf(sqrtf(s1), MINN);
    float te = tanhf(un);
    float hn = fminf(te, MAXN_F);
    float lam = hn / un;
    float gam = artanh_f(hn) / fmaxf(hn, MINN);
    float gl  = gam * lam;

    float4 up;
    up.x = fmaxf(u.x, 0.f); up.y = fmaxf(u.y, 0.f);
    up.z = fmaxf(u.z, 0.f); up.w = fmaxf(u.w, 0.f);
    float s2 = up.x * up.x + up.y * up.y + up.z * up.z + up.w * up.w;
    #pragma unroll
    for (int off = 16; off; off >>= 1) s2 += __shfl_xor_sync(0xffffffffu, s2, off);
    float m  = fmaxf(gl * sqrtf(s2), MINN);
    float tm = tanhf(m);
    float F  = fminf(tm, MAXN_F) / m * gl;

    float4 o;
    o.x = F * up.x; o.y = F * up.y; o.z = F * up.z; o.w = F * up.w;
    *(float4*)&out[(size_t)gw * 128 + j4] = o;
}

// ------------------------------------------- fallback (shapes > static) ----
__global__ void k_zero(int n4) {
    int i = blockIdx.x * blockDim.x + threadIdx.x;
    if (i < n4) ((float4*)g_agg)[i] = make_float4(0.f, 0.f, 0.f, 0.f);
}

__global__ __launch_bounds__(256)
void k_scatter(const int* __restrict__ adj, const float* __restrict__ w,
               int e, int n) {
    int gw   = (blockIdx.x * blockDim.x + threadIdx.x) >> 5;
    int lane = threadIdx.x & 31;
    if (gw >= e) return;
    int s = 0, r = 0; float we = 0.f;
    if (lane == 0) {
        s  = __ldg(&adj[gw]);
        r  = __ldg(&adj[e + gw]);
        we = __ldg(&w[gw]);
    }
    s  = __shfl_sync(0xffffffffu, s, 0);
    r  = __shfl_sync(0xffffffffu, r, 0);
    we = __shfl_sync(0xffffffffu, we, 0);
    if ((unsigned)s >= (unsigned)n || (unsigned)r >= (unsigned)n) return;
    float4 v = *(const float4*)&g_ht[(size_t)s * 128 + lane * 4];
    v.x *= we; v.y *= we; v.z *= we; v.w *= we;
    float* dst = &g_agg[(size_t)r * 128 + lane * 4];
    asm volatile("red.global.add.v4.f32 [%0], {%1, %2, %3, %4};"
                 :: "l"(dst), "f"(v.x), "f"(v.y), "f"(v.z), "f"(v.w)
                 : "memory");
}

__global__ __launch_bounds__(256)
void k_final(float* __restrict__ out, int n) {
    int gw   = (blockIdx.x * blockDim.x + threadIdx.x) >> 5;
    int lane = threadIdx.x & 31;
    if (gw >= n) return;
    float4 u = *(const float4*)&g_agg[(size_t)gw * 128 + lane * 4];
    float s1 = u.x * u.x + u.y * u.y + u.z * u.z + u.w * u.w;
    #pragma unroll
    for (int off = 16; off; off >>= 1) s1 += __shfl_xor_sync(0xffffffffu, s1, off);
    float un = fmaxf(sqrtf(s1), MINN);
    float te = tanhf(un);
    float hn = fminf(te, MAXN_F);
    float lam = hn / un;
    float gam = artanh_f(hn) / fmaxf(hn, MINN);
    float gl  = gam * lam;
    float4 up;
    up.x = fmaxf(u.x, 0.f); up.y = fmaxf(u.y, 0.f);
    up.z = fmaxf(u.z, 0.f); up.w = fmaxf(u.w, 0.f);
    float s2 = up.x * up.x + up.y * up.y + up.z * up.z + up.w * up.w;
    #pragma unroll
    for (int off = 16; off; off >>= 1) s2 += __shfl_xor_sync(0xffffffffu, s2, off);
    float m  = fmaxf(gl * sqrtf(s2), MINN);
    float tm = tanhf(m);
    float F  = fminf(tm, MAXN_F) / m * gl;
    float4 o;
    o.x = F * up.x; o.y = F * up.y; o.z = F * up.z; o.w = F * up.w;
    *(float4*)&out[(size_t)gw * 128 + lane * 4] = o;
}

// adj (int32) -> float tail
__global__ void k_adjf(const int* __restrict__ adj, float* __restrict__ out, int m) {
    int i = blockIdx.x * blockDim.x + threadIdx.x;
    if (i < m) out[i] = (float)adj[i];
}

// ---------------------------------------------------------------------------
extern "C" void kernel_launch(void* const* d_in, const int* in_sizes, int n_in,
                              void* d_out, int out_size) {
    const float* x      = (const float*)d_in[0];
    const int*   adj    = (const int*)d_in[1];
    const float* w      = (const float*)d_in[2];
    const float* weight = (const float*)d_in[3];
    const float* bias   = (const float*)d_in[4];

    const int d = in_sizes[4];            // 128
    const int n = in_sizes[0] / d;        // 50000
    const int e = in_sizes[2];            // 800000
    float* out = (float*)d_out;

    static cudaStream_t s2 = nullptr;
    static cudaEvent_t  evFork = nullptr, evH1 = nullptr, evGA = nullptr, evTail = nullptr;
    static bool initTried = false;
    if (!initTried) {
        initTried = true;
        if (cudaStreamCreateWithFlags(&s2, cudaStreamNonBlocking) != cudaSuccess) s2 = nullptr;
        if (cudaEventCreateWithFlags(&evFork, cudaEventDisableTiming) != cudaSuccess) evFork = nullptr;
        if (cudaEventCreateWithFlags(&evH1,   cudaEventDisableTiming) != cudaSuccess) evH1 = nullptr;
        if (cudaEventCreateWithFlags(&evGA,   cudaEventDisableTiming) != cudaSuccess) evGA = nullptr;
        if (cudaEventCreateWithFlags(&evTail, cudaEventDisableTiming) != cudaSuccess) evTail = nullptr;
    }
    const bool dual = (s2 && evFork && evH1 && evGA && evTail);

    const size_t smem = (size_t)(128 * 132 + 64 * 132 + 128) * sizeof(float);
    cudaFuncSetAttribute(k_linear, cudaFuncAttributeMaxDynamicSharedMemorySize, (int)smem);

    long long extra = (long long)out_size - (long long)n * d;

    if (dual && n <= NMAX && e <= EMAX) {
        int h1 = ((n / 2 + 63) / 64) * 64;
        if (h1 > n) h1 = n;
        const int m  = 2 * n;
        const int nb = (m + SCHUNK - 1) / SCHUNK;
        const int eth = (e + 3) / 4;              // 4 edges per thread

        cudaEventRecord(evFork, 0);
        cudaStreamWaitEvent(s2, evFork, 0);

        // --- stream B: two-bucket CSR build ---
        k_zero_cnt<<<(m + 255) / 256, 256, 0, s2>>>(m);
        k_hist<<<(eth + 255) / 256, 256, 0, s2>>>(adj, e, n, h1);
        k_scan1<<<nb, 256, 0, s2>>>(m);
        k_scan2<<<1, 32, 0, s2>>>(nb);
        k_scan3<<<(m + 255) / 256, 256, 0, s2>>>(m, nb);
        k_fill<<<(eth + 255) / 256, 256, 0, s2>>>(adj, w, e, n, h1);

        // --- stream A: linear half 1, signal, half 2 ---
        k_linear<<<h1 / 64, 256, smem>>>(x, weight, bias, 0, h1);
        cudaEventRecord(evH1, 0);
        if (h1 < n)
            k_linear<<<(n - h1 + 63) / 64, 256, smem>>>(x, weight, bias, h1, n);

        // --- stream B: gather bucket A (overlaps linear half 2) ---
        cudaStreamWaitEvent(s2, evH1, 0);
        k_gather_a<<<(n * 32 + 255) / 256, 256, 0, s2>>>(n);
        cudaEventRecord(evGA, s2);

        // stream B tail (runs under gather_B), then tail-join event
        if (extra == (long long)2 * e) {
            k_adjf<<<(int)((2LL * e + 255) / 256), 256, 0, s2>>>(adj, out + (size_t)n * d, 2 * e);
        } else if (extra > 0) {
            cudaMemcpyAsync(out + (size_t)n * d, adj,
                            (size_t)extra * sizeof(float),
                            cudaMemcpyDeviceToDevice, s2);
        }
        cudaEventRecord(evTail, s2);

        // --- stream A: join GA, gather bucket B + epilogue, join tail ---
        cudaStreamWaitEvent((cudaStream_t)0, evGA, 0);
        k_gather_b_final<<<(n * 32 + 255) / 256, 256>>>(out, n);
        cudaStreamWaitEvent((cudaStream_t)0, evTail, 0);   // full capture join
    } else {
        // serial fallback (no side stream needed)
        int n4 = n * 32;
        k_zero<<<(n4 + 255) / 256, 256>>>(n4);
        k_linear<<<(n + 63) / 64, 256, smem>>>(x, weight, bias, 0, n);
        long long sthreads = (long long)e * 32;
        k_scatter<<<(unsigned)((sthreads + 255) / 256), 256>>>(adj, w, e, n);
        k_final<<<(n * 32 + 255) / 256, 256>>>(out, n);
        if (extra == (long long)2 * e) {
            k_adjf<<<(int)((2LL * e + 255) / 256), 256>>>(adj, out + (size_t)n * d, 2 * e);
        } else if (extra > 0) {
            cudaMemcpyAsync(out + (size_t)n * d, adj,
                            (size_t)extra * sizeof(float),
                            cudaMemcpyDeviceToDevice);
        }
    }
}

// round 17
// speedup vs baseline: 1.2819x; 1.2819x over previous
#include <cuda_runtime.h>
#include <cuda_fp16.h>
#include <cstdint>

// ---------------------------------------------------------------------------
// HGCN layer, c_in = c_out = 1.  (Round-13 topology + fp16 ht mirror)
//   stream A (default): k_linear (bias folded in, writes ht fp32 + fp16) --\
//   stream B (forked) : CSR build (zero/hist/scan1-3/fill) + adj tail ------+--> k_gather_final (fp16 reads)
// adj is int32 (JAX w/o x64 downcasts int64 -> int32).
// ---------------------------------------------------------------------------

#define NMAX   50000
#define EMAX   800000
#define MAXN_F 0.996f     // (1 - 4e-3)/sqrt(c), c = 1
#define MINN   1e-15f
#define SCHUNK 1024
#define NBMAX  ((NMAX + SCHUNK - 1) / SCHUNK + 2)

__device__ __align__(16) float   g_ht [(size_t)NMAX * 128];   // fp32 (fallback path)
__device__ __align__(16) __half2 g_hth[(size_t)NMAX * 64];    // fp16 mirror (gather path)
__device__ __align__(16) float   g_agg[(size_t)NMAX * 128];   // fallback only
__device__ __align__(16) int g_cnt[NMAX];
__device__ int   g_off[NMAX + 1];
__device__ int   g_cur[NMAX];
__device__ int   g_bsum[NBMAX];
__device__ __align__(8) int2 g_pair[EMAX];   // .x = src, .y = bitcast(weight)

__device__ __forceinline__ float artanh_f(float v) {
    v = fminf(fmaxf(v, -1.0f + 1e-7f), 1.0f - 1e-7f);
    return 0.5f * (log1pf(v) - log1pf(-v));
}

// ------------------------------------------------------- fused HypLinear ----
// bias -> hyp-bias transform computed per-block; GEMM k-unrolled x4.
__global__ __launch_bounds__(256, 2)
void k_linear(const float* __restrict__ x, const float* __restrict__ weight,
              const float* __restrict__ bias, int n) {
    extern __shared__ float sm[];
    float* ws  = sm;                        // [128][132]  ws[k*132+j] = W[j][k]
    float* xs  = sm + 128 * 132;            // [64][132]
    float* hbs = sm + 128 * 132 + 64 * 132; // [128]
    __shared__ float s_red[4];
    const int tid  = threadIdx.x;
    const int row0 = blockIdx.x * 64;
    const int lane = tid & 31;

    float bv = (tid < 128) ? bias[tid] : 0.0f;
    {
        float ss = bv * bv;
        #pragma unroll
        for (int off = 16; off; off >>= 1) ss += __shfl_xor_sync(0xffffffffu, ss, off);
        if (tid < 128 && lane == 0) s_red[tid >> 5] = ss;
    }
    __syncthreads();
    const float btot = s_red[0] + s_red[1] + s_red[2] + s_red[3];
    const float bn   = fmaxf(sqrtf(btot), MINN);
    const float teb  = tanhf(bn);
    float bf = teb / bn;
    if (teb > MAXN_F) bf *= MAXN_F / fmaxf(teb, MINN);
    const float hnb  = fminf(teb, MAXN_F);
    const float hbsq = hnb * hnb;
    if (tid < 128) hbs[tid] = bf * bv;

    for (int i = tid; i < 128 * 128; i += 256) {
        int j = i >> 7, k = i & 127;
        ws[k * 132 + j] = weight[i];
    }
    for (int i = tid; i < 64 * 128; i += 256) {
        int r = i >> 7, k = i & 127;
        int gr = row0 + r;
        xs[r * 132 + k] = (gr < n) ? x[(size_t)gr * 128 + k] : 0.0f;
    }
    __syncthreads();

    const int w = tid >> 5;
    const int j0 = lane * 4;

    float x2[8];
    #pragma unroll
    for (int i = 0; i < 8; i++) {
        float4 xv = *(const float4*)&xs[(w * 8 + i) * 132 + j0];
        float p = xv.x * xv.x + xv.y * xv.y + xv.z * xv.z + xv.w * xv.w;
        #pragma unroll
        for (int off = 16; off; off >>= 1) p += __shfl_xor_sync(0xffffffffu, p, off);
        x2[i] = p;
    }

    float acc[8][4];
    #pragma unroll
    for (int i = 0; i < 8; i++)
        acc[i][0] = acc[i][1] = acc[i][2] = acc[i][3] = 0.f;

    for (int k = 0; k < 128; k += 4) {
        float4 b0 = *(const float4*)&ws[(k + 0) * 132 + j0];
        float4 b1 = *(const float4*)&ws[(k + 1) * 132 + j0];
        float4 b2 = *(const float4*)&ws[(k + 2) * 132 + j0];
        float4 b3 = *(const float4*)&ws[(k + 3) * 132 + j0];
        #pragma unroll
        for (int i = 0; i < 8; i++) {
            float4 a = *(const float4*)&xs[(w * 8 + i) * 132 + k];
            acc[i][0] = fmaf(a.x, b0.x, acc[i][0]);
            acc[i][1] = fmaf(a.x, b0.y, acc[i][1]);
            acc[i][2] = fmaf(a.x, b0.z, acc[i][2]);
            acc[i][3] = fmaf(a.x, b0.w, acc[i][3]);
            acc[i][0] = fmaf(a.y, b1.x, acc[i][0]);
            acc[i][1] = fmaf(a.y, b1.y, acc[i][1]);
            acc[i][2] = fmaf(a.y, b1.z, acc[i][2]);
            acc[i][3] = fmaf(a.y, b1.w, acc[i][3]);
            acc[i][0] = fmaf(a.z, b2.x, acc[i][0]);
            acc[i][1] = fmaf(a.z, b2.y, acc[i][1]);
            acc[i][2] = fmaf(a.z, b2.z, acc[i][2]);
            acc[i][3] = fmaf(a.z, b2.w, acc[i][3]);
            acc[i][0] = fmaf(a.w, b3.x, acc[i][0]);
            acc[i][1] = fmaf(a.w, b3.y, acc[i][1]);
            acc[i][2] = fmaf(a.w, b3.z, acc[i][2]);
            acc[i][3] = fmaf(a.w, b3.w, acc[i][3]);
        }
    }

    const float hb0 = hbs[j0 + 0], hb1 = hbs[j0 + 1],
                hb2c = hbs[j0 + 2], hb3 = hbs[j0 + 3];

    #pragma unroll
    for (int i = 0; i < 8; i++) {
        float sq = acc[i][0] * acc[i][0] + acc[i][1] * acc[i][1]
                 + acc[i][2] * acc[i][2] + acc[i][3] * acc[i][3];
        float db = acc[i][0] * hb0 + acc[i][1] * hb1
                 + acc[i][2] * hb2c + acc[i][3] * hb3;
        #pragma unroll
        for (int off = 16; off; off >>= 1) {
            sq += __shfl_xor_sync(0xffffffffu, sq, off);
            db += __shfl_xor_sync(0xffffffffu, db, off);
        }
        float xn  = fmaxf(sqrtf(x2[i]), MINN);
        float atx = artanh_f(xn);
        float mxn = fmaxf(sqrtf(sq), MINN);
        float t   = tanhf(mxn / xn * atx);
        float beta = t;
        if (fabsf(t) > MAXN_F) beta = copysignf(MAXN_F, t);
        float xy  = beta * (db / mxn);
        float b2  = beta * beta;
        float A   = 1.f + 2.f * xy + hbsq;
        float B   = 1.f - b2;
        float den = fmaxf(1.f + 2.f * xy + b2 * hbsq, MINN);
        float pc  = A * beta / (mxn * den);
        float qc  = B / den;
        float h2 = pc * pc * sq + 2.f * pc * qc * db + qc * qc * hbsq;
        float hn = fmaxf(sqrtf(h2), MINN);
        if (hn > MAXN_F) { float sc = MAXN_F / hn; pc *= sc; qc *= sc; hn = MAXN_F; }
        float gam = artanh_f(hn) / hn;
        float P = gam * pc, Q = gam * qc;

        int gr = row0 + w * 8 + i;
        if (gr < n) {
            float4 o;
            o.x = P * acc[i][0] + Q * hb0;
            o.y = P * acc[i][1] + Q * hb1;
            o.z = P * acc[i][2] + Q * hb2c;
            o.w = P * acc[i][3] + Q * hb3;
            *(float4*)&g_ht[(size_t)gr * 128 + j0] = o;
            // fp16 mirror for the gather path
            __half2 hpk[2];
            hpk[0] = __floats2half2_rn(o.x, o.y);
            hpk[1] = __floats2half2_rn(o.z, o.w);
            *(uint2*)&g_hth[(size_t)gr * 64 + lane * 2] = *(uint2*)hpk;
        }
    }
}

// ------------------------------------------------------------- CSR build ---
__global__ void k_zero_cnt(int n) {
    int i = blockIdx.x * blockDim.x + threadIdx.x;
    if (i < n) g_cnt[i] = 0;
}

__global__ void k_hist(const int* __restrict__ adj, int e, int n) {
    int i = blockIdx.x * blockDim.x + threadIdx.x;
    if (i >= e) return;
    int r = adj[e + i];
    if ((unsigned)r < (unsigned)n) atomicAdd(&g_cnt[r], 1);
}

__global__ __launch_bounds__(256)
void k_scan1(int n) {
    __shared__ int wsum[8];
    int blk = blockIdx.x, tid = threadIdx.x;
    int lane = tid & 31, wid = tid >> 5;
    int base = blk * SCHUNK + tid * 4;

    int v0 = 0, v1 = 0, v2 = 0, v3 = 0;
    if (base + 3 < n) {
        int4 t = *(const int4*)&g_cnt[base];
        v0 = t.x; v1 = t.y; v2 = t.z; v3 = t.w;
    } else {
        if (base + 0 < n) v0 = g_cnt[base + 0];
        if (base + 1 < n) v1 = g_cnt[base + 1];
        if (base + 2 < n) v2 = g_cnt[base + 2];
    }
    int tsum = v0 + v1 + v2 + v3;
    int x = tsum;
    #pragma unroll
    for (int off = 1; off < 32; off <<= 1) {
        int y = __shfl_up_sync(0xffffffffu, x, off);
        if (lane >= off) x += y;
    }
    if (lane == 31) wsum[wid] = x;
    __syncthreads();
    if (tid < 32) {
        int t = (tid < 8) ? wsum[tid] : 0;
        #pragma unroll
        for (int off = 1; off < 8; off <<= 1) {
            int y = __shfl_up_sync(0xffffffffu, t, off);
            if (lane >= off) t += y;
        }
        if (tid < 8) wsum[tid] = t;
    }
    __syncthreads();
    int excl = ((wid == 0) ? 0 : wsum[wid - 1]) + x - tsum;
    if (base + 0 < n) g_off[base + 0] = excl;  excl += v0;
    if (base + 1 < n) g_off[base + 1] = excl;  excl += v1;
    if (base + 2 < n) g_off[base + 2] = excl;  excl += v2;
    if (base + 3 < n) g_off[base + 3] = excl;
    __syncthreads();
    if (tid == 0) g_bsum[blk] = wsum[7];
}

__global__ void k_scan2(int nb) {
    int lane = threadIdx.x;   // 32 threads
    int carry = 0;
    for (int base = 0; base < nb; base += 32) {
        int v = (base + lane < nb) ? g_bsum[base + lane] : 0;
        int x = v;
        #pragma unroll
        for (int off = 1; off < 32; off <<= 1) {
            int y = __shfl_up_sync(0xffffffffu, x, off);
            if (lane >= off) x += y;
        }
        int excl = carry + x - v;
        if (base + lane < nb) g_bsum[base + lane] = excl;
        carry += __shfl_sync(0xffffffffu, x, 31);
    }
    if (lane == 0) g_bsum[nb] = carry;   // grand total
}

__global__ void k_scan3(int n, int nb) {
    int i = blockIdx.x * blockDim.x + threadIdx.x;
    if (i < n) {
        int v = g_off[i] + g_bsum[i / SCHUNK];
        g_off[i] = v;
        g_cur[i] = v;
    }
    if (i == 0) g_off[n] = g_bsum[nb];
}

__global__ void k_fill(const int* __restrict__ adj, const float* __restrict__ w,
                       int e, int n) {
    int i = blockIdx.x * blockDim.x + threadIdx.x;
    if (i >= e) return;
    int s = adj[i];
    int r = adj[e + i];
    if ((unsigned)s >= (unsigned)n || (unsigned)r >= (unsigned)n) return;
    int pos = atomicAdd(&g_cur[r], 1);
    g_pair[pos] = make_int2(s, __float_as_int(w[i]));
}

// ----------------------------------------------- gather + epilogue fused ---
// one warp per destination row; fp16 ht reads (256 B/row), chunks of 8 (MLP=8).
__global__ __launch_bounds__(256)
void k_gather_final(float* __restrict__ out, int n) {
    int gw   = (blockIdx.x * blockDim.x + threadIdx.x) >> 5;
    int lane = threadIdx.x & 31;
    if (gw >= n) return;
    int beg = g_off[gw], end = g_off[gw + 1];
    const int hoff = lane * 2;   // half2 index within 64-wide row

    float4 u = make_float4(0.f, 0.f, 0.f, 0.f);
    for (int j = beg; j < end; j += 8) {
        int cnt = end - j; if (cnt > 8) cnt = 8;
        int2 p = make_int2(0, 0);
        if (lane < cnt) p = g_pair[j + lane];
        int srcs[8]; float wts[8];
        #pragma unroll
        for (int t = 0; t < 8; t++) {
            srcs[t] = __shfl_sync(0xffffffffu, p.x, t);
            wts[t]  = __int_as_float(__shfl_sync(0xffffffffu, p.y, t));
        }
        uint2 pv[8];
        #pragma unroll
        for (int t = 0; t < 8; t++)
            if (t < cnt) pv[t] = *(const uint2*)&g_hth[(size_t)srcs[t] * 64 + hoff];
        #pragma unroll
        for (int t = 0; t < 8; t++)
            if (t < cnt) {
                __half2 h01 = *(__half2*)&pv[t].x;
                __half2 h23 = *(__half2*)&pv[t].y;
                float2 f01 = __half22float2(h01);
                float2 f23 = __half22float2(h23);
                u.x = fmaf(wts[t], f01.x, u.x);
                u.y = fmaf(wts[t], f01.y, u.y);
                u.z = fmaf(wts[t], f23.x, u.z);
                u.w = fmaf(wts[t], f23.y, u.w);
            }
    }

    // epilogue: proj(expmap0(u)) -> relu(logmap0) -> proj(expmap0)
    float s1 = u.x * u.x + u.y * u.y + u.z * u.z + u.w * u.w;
    #pragma unroll
    for (int off = 16; off; off >>= 1) s1 += __shfl_xor_sync(0xffffffffu, s1, off);
    float un = fmaxf(sqrtf(s1), MINN);
    float te = tanhf(un);
    float hn = fminf(te, MAXN_F);
    float lam = hn / un;
    float gam = artanh_f(hn) / fmaxf(hn, MINN);
    float gl  = gam * lam;               // logmap0 factor, >= 0

    float4 up;
    up.x = fmaxf(u.x, 0.f); up.y = fmaxf(u.y, 0.f);
    up.z = fmaxf(u.z, 0.f); up.w = fmaxf(u.w, 0.f);
    float s2 = up.x * up.x + up.y * up.y + up.z * up.z + up.w * up.w;
    #pragma unroll
    for (int off = 16; off; off >>= 1) s2 += __shfl_xor_sync(0xffffffffu, s2, off);
    float m  = fmaxf(gl * sqrtf(s2), MINN);
    float tm = tanhf(m);
    float F  = fminf(tm, MAXN_F) / m * gl;

    float4 o;
    o.x = F * up.x; o.y = F * up.y; o.z = F * up.z; o.w = F * up.w;
    *(float4*)&out[(size_t)gw * 128 + lane * 4] = o;
}

// ------------------------------------------- fallback (shapes > static) ----
__global__ void k_zero(int n4) {
    int i = blockIdx.x * blockDim.x + threadIdx.x;
    if (i < n4) ((float4*)g_agg)[i] = make_float4(0.f, 0.f, 0.f, 0.f);
}

__global__ __launch_bounds__(256)
void k_scatter(const int* __restrict__ adj, const float* __restrict__ w,
               int e, int n) {
    int gw   = (blockIdx.x * blockDim.x + threadIdx.x) >> 5;
    int lane = threadIdx.x & 31;
    if (gw >= e) return;
    int s = 0, r = 0; float we = 0.f;
    if (lane == 0) {
        s  = __ldg(&adj[gw]);
        r  = __ldg(&adj[e + gw]);
        we = __ldg(&w[gw]);
    }
    s  = __shfl_sync(0xffffffffu, s, 0);
    r  = __shfl_sync(0xffffffffu, r, 0);
    we = __shfl_sync(0xffffffffu, we, 0);
    if ((unsigned)s >= (unsigned)n || (unsigned)r >= (unsigned)n) return;
    float4 v = *(const float4*)&g_ht[(size_t)s * 128 + lane * 4];
    v.x *= we; v.y *= we; v.z *= we; v.w *= we;
    float* dst = &g_agg[(size_t)r * 128 + lane * 4];
    asm volatile("red.global.add.v4.f32 [%0], {%1, %2, %3, %4};"
                 :: "l"(dst), "f"(v.x), "f"(v.y), "f"(v.z), "f"(v.w)
                 : "memory");
}

__global__ __launch_bounds__(256)
void k_final(float* __restrict__ out, int n) {
    int gw   = (blockIdx.x * blockDim.x + threadIdx.x) >> 5;
    int lane = threadIdx.x & 31;
    if (gw >= n) return;
    float4 u = *(const float4*)&g_agg[(size_t)gw * 128 + lane * 4];
    float s1 = u.x * u.x + u.y * u.y + u.z * u.z + u.w * u.w;
    #pragma unroll
    for (int off = 16; off; off >>= 1) s1 += __shfl_xor_sync(0xffffffffu, s1, off);
    float un = fmaxf(sqrtf(s1), MINN);
    float te = tanhf(un);
    float hn = fminf(te, MAXN_F);
    float lam = hn / un;
    float gam = artanh_f(hn) / fmaxf(hn, MINN);
    float gl  = gam * lam;
    float4 up;
    up.x = fmaxf(u.x, 0.f); up.y = fmaxf(u.y, 0.f);
    up.z = fmaxf(u.z, 0.f); up.w = fmaxf(u.w, 0.f);
    float s2 = up.x * up.x + up.y * up.y + up.z * up.z + up.w * up.w;
    #pragma unroll
    for (int off = 16; off; off >>= 1) s2 += __shfl_xor_sync(0xffffffffu, s2, off);
    float m  = fmaxf(gl * sqrtf(s2), MINN);
    float tm = tanhf(m);
    float F  = fminf(tm, MAXN_F) / m * gl;
    float4 o;
    o.x = F * up.x; o.y = F * up.y; o.z = F * up.z; o.w = F * up.w;
    *(float4*)&out[(size_t)gw * 128 + lane * 4] = o;
}

// adj (int32) -> float tail, if the harness flattened the tuple to float32
__global__ void k_adjf(const int* __restrict__ adj, float* __restrict__ out, int m) {
    int i = blockIdx.x * blockDim.x + threadIdx.x;
    if (i < m) out[i] = (float)adj[i];
}

// ---------------------------------------------------------------------------
extern "C" void kernel_launch(void* const* d_in, const int* in_sizes, int n_in,
                              void* d_out, int out_size) {
    const float* x      = (const float*)d_in[0];
    const int*   adj    = (const int*)d_in[1];
    const float* w      = (const float*)d_in[2];
    const float* weight = (const float*)d_in[3];
    const float* bias   = (const float*)d_in[4];

    const int d = in_sizes[4];            // 128
    const int n = in_sizes[0] / d;        // 50000
    const int e = in_sizes[2];            // 800000
    float* out = (float*)d_out;

    // one-time side stream + events (created on the uncaptured correctness
    // call; reused by the captured call -> graph-legal fork/join)
    static cudaStream_t s2 = nullptr;
    static cudaEvent_t  evFork = nullptr, evJoin = nullptr;
    static bool initTried = false;
    if (!initTried) {
        initTried = true;
        if (cudaStreamCreateWithFlags(&s2, cudaStreamNonBlocking) != cudaSuccess) s2 = nullptr;
        if (cudaEventCreateWithFlags(&evFork, cudaEventDisableTiming) != cudaSuccess) evFork = nullptr;
        if (cudaEventCreateWithFlags(&evJoin, cudaEventDisableTiming) != cudaSuccess) evJoin = nullptr;
    }
    const bool dual = (s2 && evFork && evJoin);
    cudaStream_t sb = dual ? s2 : (cudaStream_t)0;   // CSR-build stream

    const size_t smem = (size_t)(128 * 132 + 64 * 132 + 128) * sizeof(float);
    cudaFuncSetAttribute(k_linear, cudaFuncAttributeMaxDynamicSharedMemorySize, (int)smem);

    long long extra = (long long)out_size - (long long)n * d;

    if (dual) {
        cudaEventRecord(evFork, 0);
        cudaStreamWaitEvent(s2, evFork, 0);
    }

    if (n <= NMAX && e <= EMAX) {
        // --- stream B: CSR build + output tail (independent of linear) ---
        int nb = (n + SCHUNK - 1) / SCHUNK;
        k_zero_cnt<<<(n + 255) / 256, 256, 0, sb>>>(n);
        k_hist<<<(e + 255) / 256, 256, 0, sb>>>(adj, e, n);
        k_scan1<<<nb, 256, 0, sb>>>(n);
        k_scan2<<<1, 32, 0, sb>>>(nb);
        k_scan3<<<(n + 255) / 256, 256, 0, sb>>>(n, nb);
        k_fill<<<(e + 255) / 256, 256, 0, sb>>>(adj, w, e, n);
        if (extra == (long long)2 * e) {
            k_adjf<<<(int)((2LL * e + 255) / 256), 256, 0, sb>>>(adj, out + (size_t)n * d, 2 * e);
        } else if (extra > 0) {
            cudaMemcpyAsync(out + (size_t)n * d, adj,
                            (size_t)extra * sizeof(float),
                            cudaMemcpyDeviceToDevice, sb);
        }
        if (dual) cudaEventRecord(evJoin, s2);

        // --- stream A: fused HypLinear (bias folded in) ---
        k_linear<<<(n + 63) / 64, 256, smem>>>(x, weight, bias, n);

        // --- join, then fused gather + epilogue (fp16 reads) ---
        if (dual) cudaStreamWaitEvent((cudaStream_t)0, evJoin, 0);
        k_gather_final<<<(n * 32 + 255) / 256, 256>>>(out, n);
    } else {
        // fallback: atomic scatter (zeroing + tail overlapped on stream B)
        int n4 = n * 32;
        k_zero<<<(n4 + 255) / 256, 256, 0, sb>>>(n4);
        if (extra == (long long)2 * e) {
            k_adjf<<<(int)((2LL * e + 255) / 256), 256, 0, sb>>>(adj, out + (size_t)n * d, 2 * e);
        } else if (extra > 0) {
            cudaMemcpyAsync(out + (size_t)n * d, adj,
                            (size_t)extra * sizeof(float),
                            cudaMemcpyDeviceToDevice, sb);
        }
        if (dual) cudaEventRecord(evJoin, s2);
        k_linear<<<(n + 63) / 64, 256, smem>>>(x, weight, bias, n);
        if (dual) cudaStreamWaitEvent((cudaStream_t)0, evJoin, 0);
        long long sthreads = (long long)e * 32;
        k_scatter<<<(unsigned)((sthreads + 255) / 256), 256>>>(adj, w, e, n);
        k_final<<<(n * 32 + 255) / 256, 256>>>(out, n);
    }
}